// round 1
// baseline (speedup 1.0000x reference)
#include <cuda_runtime.h>
#include <math.h>

#define BB 16
#define DD 512
#define HH 16
#define HD 32
#define LL 24
#define DFF 2048
#define NQKV 1536
#define TMAX 1024

// ---------------- device scratch (no allocations allowed) ----------------
__device__ float g_h[BB * DD];          // current hidden state
__device__ float g_attn[BB * DD];       // attention output (pre out-proj)
__device__ float g_pqkv[8 * BB * NQKV]; // qkv partials   [8][B][1536]
__device__ float g_pout[8 * BB * DD];   // outproj partials [8][B][512]
__device__ float g_pm1[8 * BB * DFF];   // mlp1 partials  [8][B][2048]
__device__ float g_pm2[16 * BB * DD];   // mlp2 partials  [16][B][512]

// ---------------- init: h <- x ----------------
__global__ void init_h_kernel(const float* __restrict__ x) {
    int i = blockIdx.x * blockDim.x + threadIdx.x;
    if (i < BB * DD) g_h[i] = x[i];
}

// ---------------- generic split-K GEMV with 16-batch accumulators -------
// part[slice][b][col] = sum_{d in slice} x[b][d] * W[d][col]
// mode 0: xsrc is finished activations [B][K]
// mode 1: xsrc is 8-way partials [8][B][K]; x[b][d] = relu(bias1[d] + sum_s p[s][b][d])
__global__ void gemv_part_kernel(const float* __restrict__ xsrc,
                                 const float* __restrict__ bias1,
                                 const float* __restrict__ W,
                                 float* __restrict__ part,
                                 int N, int K, int DS, int mode) {
    __shared__ float xs[128][20];  // [d][b], stride 20 keeps 16B alignment of xs[d][0]
    const int tid = threadIdx.x;
    const int slice = blockIdx.y;
    const int d0 = slice * DS;

    if (mode == 0) {
        for (int i = tid; i < DS * BB; i += 256) {
            int b = i / DS, d = i - b * DS;
            xs[d][b] = xsrc[(size_t)b * K + d0 + d];
        }
    } else {
        for (int i = tid; i < DS * BB; i += 256) {
            int b = i / DS, d = i - b * DS;
            int c = d0 + d;
            float v = bias1[c];
#pragma unroll
            for (int s = 0; s < 8; s++) v += xsrc[(size_t)(s * BB + b) * K + c];
            xs[d][b] = fmaxf(v, 0.0f);
        }
    }
    __syncthreads();

    const int col = blockIdx.x * 256 + tid;
    float acc[16];
#pragma unroll
    for (int b = 0; b < 16; b++) acc[b] = 0.0f;

    const float* Wp = W + (size_t)d0 * N + col;
#pragma unroll 4
    for (int d = 0; d < DS; d++) {
        float w = Wp[(size_t)d * N];
        float4 x0 = *(const float4*)&xs[d][0];
        float4 x1 = *(const float4*)&xs[d][4];
        float4 x2 = *(const float4*)&xs[d][8];
        float4 x3 = *(const float4*)&xs[d][12];
        acc[0]  += x0.x * w;  acc[1]  += x0.y * w;
        acc[2]  += x0.z * w;  acc[3]  += x0.w * w;
        acc[4]  += x1.x * w;  acc[5]  += x1.y * w;
        acc[6]  += x1.z * w;  acc[7]  += x1.w * w;
        acc[8]  += x2.x * w;  acc[9]  += x2.y * w;
        acc[10] += x2.z * w;  acc[11] += x2.w * w;
        acc[12] += x3.x * w;  acc[13] += x3.y * w;
        acc[14] += x3.z * w;  acc[15] += x3.w * w;
    }

    float* p = part + (size_t)(slice * BB) * N + col;
#pragma unroll
    for (int b = 0; b < 16; b++) p[(size_t)b * N] = acc[b];
}

// ---------------- attention: merge qkv partials + softmax-attn ----------
// grid (H, B), 256 threads. New-token k/v computed here (cache never written;
// equivalent under mask pos <= kv_len).
__global__ void attn_kernel(const float* __restrict__ pqkv,
                            const float* __restrict__ bq,
                            const float* __restrict__ Kc,
                            const float* __restrict__ Vc,
                            const int* __restrict__ kvlen,
                            float* __restrict__ out) {
    const int h = blockIdx.x, b = blockIdx.y;
    const int tid = threadIdx.x, wid = tid >> 5, lane = tid & 31;

    __shared__ float qs[HD], kns[HD], vns[HD];
    __shared__ float sc[TMAX + 1];
    __shared__ float red[8][HD];
    __shared__ float rmax[8], rsum[8];

    // merge qkv partials for this head's 96 columns
    if (tid < 96) {
        int which = tid >> 5, lj = tid & 31;
        int col = which * DD + h * HD + lj;
        float v = bq[col];
#pragma unroll
        for (int s = 0; s < 8; s++) v += pqkv[(size_t)(s * BB + b) * NQKV + col];
        if (which == 0) qs[lj] = v;
        else if (which == 1) kns[lj] = v;
        else vns[lj] = v;
    }
    __syncthreads();

    const int T = kvlen[b];
    const float scale = 0.17677669529663687f;  // 1/sqrt(32)
    const float* Kb = Kc + ((size_t)b * HH + h) * TMAX * HD;
    const float* Vb = Vc + ((size_t)b * HH + h) * TMAX * HD;
    const float qv = qs[lane];

    // scores: warp per timestep, 128B coalesced K row loads
#pragma unroll 4
    for (int t = wid; t < T; t += 8) {
        float p = qv * Kb[(size_t)t * HD + lane];
#pragma unroll
        for (int o = 16; o; o >>= 1) p += __shfl_xor_sync(0xffffffffu, p, o);
        if (lane == 0) sc[t] = p * scale;
    }
    if (wid == 0) {  // new token at position T
        float p = qv * kns[lane];
#pragma unroll
        for (int o = 16; o; o >>= 1) p += __shfl_xor_sync(0xffffffffu, p, o);
        if (lane == 0) sc[T] = p * scale;
    }
    __syncthreads();

    // block max
    float m = -1e30f;
    for (int t = tid; t <= T; t += 256) m = fmaxf(m, sc[t]);
#pragma unroll
    for (int o = 16; o; o >>= 1) m = fmaxf(m, __shfl_xor_sync(0xffffffffu, m, o));
    if (lane == 0) rmax[wid] = m;
    __syncthreads();
    if (tid == 0) {
        float mm = rmax[0];
        for (int w = 1; w < 8; w++) mm = fmaxf(mm, rmax[w]);
        rmax[0] = mm;
    }
    __syncthreads();
    m = rmax[0];

    // exp + sum
    float s = 0.0f;
    for (int t = tid; t <= T; t += 256) {
        float e = __expf(sc[t] - m);
        sc[t] = e;
        s += e;
    }
#pragma unroll
    for (int o = 16; o; o >>= 1) s += __shfl_xor_sync(0xffffffffu, s, o);
    if (lane == 0) rsum[wid] = s;
    __syncthreads();
    if (tid == 0) {
        float ss = rsum[0];
        for (int w = 1; w < 8; w++) ss += rsum[w];
        rsum[0] = ss;
    }
    __syncthreads();
    const float S = rsum[0];

    // V accumulation: warp per timestep, lane = head dim
    float acc = 0.0f;
#pragma unroll 4
    for (int t = wid; t < T; t += 8) acc += sc[t] * Vb[(size_t)t * HD + lane];
    if (wid == 0) acc += sc[T] * vns[lane];
    red[wid][lane] = acc;
    __syncthreads();
    if (wid == 0) {
        float o = acc;
#pragma unroll
        for (int w = 1; w < 8; w++) o += red[w][lane];
        out[(size_t)b * DD + h * HD + lane] = o / S;
    }
}

// ---------------- merge partials + bias + residual + LayerNorm ----------
// grid B, 512 threads. Writes g_h (and optionally d_out).
__global__ void ln_kernel(const float* __restrict__ part, int S,
                          const float* __restrict__ bias,
                          const float* __restrict__ gam,
                          const float* __restrict__ bet,
                          float* __restrict__ hbuf,
                          float* __restrict__ out2) {
    const int b = blockIdx.x, j = threadIdx.x;
    const int lane = j & 31, wid = j >> 5;

    float v = bias[j] + hbuf[(size_t)b * DD + j];
    for (int s = 0; s < S; s++) v += part[(size_t)(s * BB + b) * DD + j];

    __shared__ float rs[16], rq[16], mv[2];
    float s1 = v, s2 = v * v;
#pragma unroll
    for (int o = 16; o; o >>= 1) {
        s1 += __shfl_xor_sync(0xffffffffu, s1, o);
        s2 += __shfl_xor_sync(0xffffffffu, s2, o);
    }
    if (lane == 0) { rs[wid] = s1; rq[wid] = s2; }
    __syncthreads();
    if (j == 0) {
        float a = 0.0f, q = 0.0f;
        for (int w = 0; w < 16; w++) { a += rs[w]; q += rq[w]; }
        float mean = a / DD;
        mv[0] = mean;
        mv[1] = rsqrtf(q / DD - mean * mean + 1e-5f);
    }
    __syncthreads();
    float o = (v - mv[0]) * mv[1] * gam[j] + bet[j];
    hbuf[(size_t)b * DD + j] = o;
    if (out2) out2[(size_t)b * DD + j] = o;
}

// ---------------- launcher ----------------
extern "C" void kernel_launch(void* const* d_in, const int* in_sizes, int n_in,
                              void* d_out, int out_size) {
    (void)in_sizes; (void)n_in; (void)out_size;
    const float* x    = (const float*)d_in[0];
    const float* kc   = (const float*)d_in[1];
    const float* vc   = (const float*)d_in[2];
    const float* ln1g = (const float*)d_in[3];
    const float* ln1b = (const float*)d_in[4];
    const float* qkvw = (const float*)d_in[5];
    const float* qkvb = (const float*)d_in[6];
    const float* outw = (const float*)d_in[7];
    const float* outb = (const float*)d_in[8];
    const float* ln2g = (const float*)d_in[9];
    const float* ln2b = (const float*)d_in[10];
    const float* w1   = (const float*)d_in[11];
    const float* b1   = (const float*)d_in[12];
    const float* w2   = (const float*)d_in[13];
    const float* b2   = (const float*)d_in[14];
    // d_in[15] = attn_mask (recomputed from kv_cache_len), d_in[17] = batch_indices (arange)
    const int* kvlen  = (const int*)d_in[16];

    static float *p_h = nullptr, *p_attn, *p_pqkv, *p_pout, *p_pm1, *p_pm2;
    if (!p_h) {
        cudaGetSymbolAddress((void**)&p_h,    g_h);
        cudaGetSymbolAddress((void**)&p_attn, g_attn);
        cudaGetSymbolAddress((void**)&p_pqkv, g_pqkv);
        cudaGetSymbolAddress((void**)&p_pout, g_pout);
        cudaGetSymbolAddress((void**)&p_pm1,  g_pm1);
        cudaGetSymbolAddress((void**)&p_pm2,  g_pm2);
    }

    init_h_kernel<<<16, 512>>>(x);

    for (int l = 0; l < LL; l++) {
        const size_t kvoff = (size_t)l * BB * HH * TMAX * HD;

        // qkv GEMV: N=1536, K=512, 8 slices of 64 -> 48 blocks
        gemv_part_kernel<<<dim3(6, 8), 256>>>(
            p_h, nullptr, qkvw + (size_t)l * DD * NQKV, p_pqkv, NQKV, DD, 64, 0);

        // attention (merges qkv partials itself)
        attn_kernel<<<dim3(HH, BB), 256>>>(
            p_pqkv, qkvb + (size_t)l * NQKV, kc + kvoff, vc + kvoff, kvlen, p_attn);

        // out projection: N=512, K=512, 8 slices -> 16 blocks
        gemv_part_kernel<<<dim3(2, 8), 256>>>(
            p_attn, nullptr, outw + (size_t)l * DD * DD, p_pout, DD, DD, 64, 0);

        // merge + bias + residual + LN1
        ln_kernel<<<BB, DD>>>(p_pout, 8, outb + (size_t)l * DD,
                              ln1g + (size_t)l * DD, ln1b + (size_t)l * DD,
                              p_h, nullptr);

        // mlp1: N=2048, K=512, 8 slices -> 64 blocks (relu deferred to mlp2 preload)
        gemv_part_kernel<<<dim3(8, 8), 256>>>(
            p_h, nullptr, w1 + (size_t)l * DD * DFF, p_pm1, DFF, DD, 64, 0);

        // mlp2: N=512, K=2048, 16 slices of 128 -> 32 blocks; mode 1 fuses
        // (sum-of-8-partials + bias + relu) into the x preload
        gemv_part_kernel<<<dim3(2, 16), 256>>>(
            p_pm1, b1 + (size_t)l * DFF, w2 + (size_t)l * DFF * DD, p_pm2, DD, DFF, 128, 1);

        // merge + bias + residual + LN2 (last layer also writes d_out)
        ln_kernel<<<BB, DD>>>(p_pm2, 16, b2 + (size_t)l * DD,
                              ln2g + (size_t)l * DD, ln2b + (size_t)l * DD,
                              p_h, (l == LL - 1) ? (float*)d_out : nullptr);
    }
}

// round 2
// speedup vs baseline: 2.2678x; 2.2678x over previous
#include <cuda_runtime.h>
#include <math.h>

#define BB 16
#define DD 512
#define HH 16
#define HD 32
#define LL 24
#define DFF 2048
#define NQKV 1536
#define TMAX 1024
#define NTHREADS 256

// ---------------- device scratch ----------------
__device__ float g_h[BB * DD];
__device__ float g_qkv[BB * NQKV];
__device__ float g_attn[BB * DD];
__device__ float g_ao[BB * DD];
__device__ float g_act[BB * DFF];
__device__ float g_p2[4 * BB * DD];
__device__ unsigned g_bar_count;
__device__ volatile unsigned g_bar_gen;

// ---------------- software grid barrier (all blocks resident) ----------------
__device__ __forceinline__ void gsync() {
    __syncthreads();
    if (threadIdx.x == 0) {
        unsigned gen = g_bar_gen;
        __threadfence();
        if (atomicAdd(&g_bar_count, 1u) == gridDim.x - 1) {
            g_bar_count = 0;
            __threadfence();
            g_bar_gen = gen + 1;
        } else {
            while (g_bar_gen == gen) { }
            __threadfence();
        }
    }
    __syncthreads();
}

// ---------------- full-K GEMV block: 32 cols x 8 batches, K=512 slice ------
// 8 warps each handle 64 K-dims; smem cross-warp reduction finalizes output.
__device__ void gemv_block(const float* __restrict__ x, int ldx, int d0,
                           const float* __restrict__ W, int N,
                           const float* __restrict__ bias, int relu,
                           float* __restrict__ out, int ldo,
                           int b0, int c0, float* sm) {
    float* xs  = sm;               // [512][12] (stride 12 floats = 48B, 16B aligned)
    float* red = sm + 512 * 12;    // [256][9]
    const int tid = threadIdx.x;

    // preload x[b0..b0+7][d0..d0+511] -> xs[d][bb]
    for (int i = tid; i < 8 * 512; i += NTHREADS) {
        int bb = i >> 9, d = i & 511;
        xs[d * 12 + bb] = x[(size_t)(b0 + bb) * ldx + d0 + d];
    }
    __syncthreads();

    const int lane = tid & 31, w = tid >> 5;
    const float* Wp = W + (size_t)(d0 + w * 64) * N + c0 + lane;
    const float* xp = xs + (size_t)(w * 64) * 12;
    float a0 = 0, a1 = 0, a2 = 0, a3 = 0, a4 = 0, a5 = 0, a6 = 0, a7 = 0;
#pragma unroll 8
    for (int d = 0; d < 64; d++) {
        float wv = Wp[(size_t)d * N];
        float4 xa = *(const float4*)(xp + d * 12);
        float4 xb = *(const float4*)(xp + d * 12 + 4);
        a0 += xa.x * wv; a1 += xa.y * wv; a2 += xa.z * wv; a3 += xa.w * wv;
        a4 += xb.x * wv; a5 += xb.y * wv; a6 += xb.z * wv; a7 += xb.w * wv;
    }
    float* rp = red + (size_t)tid * 9;
    rp[0] = a0; rp[1] = a1; rp[2] = a2; rp[3] = a3;
    rp[4] = a4; rp[5] = a5; rp[6] = a6; rp[7] = a7;
    __syncthreads();

    // reduce 8 warps: thread -> (col, batch)
    const int cc = tid & 31, bb = tid >> 5;
    float v = 0.f;
#pragma unroll
    for (int w2 = 0; w2 < 8; w2++) v += red[(size_t)(w2 * 32 + cc) * 9 + bb];
    if (bias) v += bias[c0 + cc];
    if (relu) v = fmaxf(v, 0.f);
    out[(size_t)(b0 + bb) * ldo + c0 + cc] = v;
    __syncthreads();
}

// ---------------- attention block: one (b, h) ----------------
__device__ void attn_block(const float* __restrict__ Kc, const float* __restrict__ Vc,
                           const int* __restrict__ kvlen, int b, int h, float* sm) {
    float* sc   = sm;          // [1056]
    float* qs   = sm + 1056;   // [32]
    float* redv = sm + 1088;   // [8][32]
    float* rr   = sm + 1344;   // [8] warp max | sum, [2] final
    float* fin  = sm + 1352;

    const int tid = threadIdx.x, wid = tid >> 5, lane = tid & 31;
    const int T = kvlen[b];
    const float scale = 0.17677669529663687f; // 1/sqrt(32)

    if (tid < HD) qs[tid] = g_qkv[(size_t)b * NQKV + h * HD + tid];
    __syncthreads();

    const float* Kb = Kc + ((size_t)b * HH + h) * TMAX * HD;
    const float* Vb = Vc + ((size_t)b * HH + h) * TMAX * HD;
    const float* kn = g_qkv + (size_t)b * NQKV + DD + h * HD;
    const float* vn = g_qkv + (size_t)b * NQKV + 2 * DD + h * HD;

    // scores: thread per timestep, float4 row loads
    for (int t = tid; t <= T; t += NTHREADS) {
        const float* kp = (t < T) ? (Kb + (size_t)t * HD) : kn;
        float s = 0.f;
#pragma unroll
        for (int i = 0; i < 8; i++) {
            float4 k4 = *(const float4*)(kp + i * 4);
            float4 q4 = *(const float4*)(qs + i * 4);
            s += k4.x * q4.x + k4.y * q4.y + k4.z * q4.z + k4.w * q4.w;
        }
        sc[t] = s * scale;
    }
    __syncthreads();

    // block max
    float m = -1e30f;
    for (int t = tid; t <= T; t += NTHREADS) m = fmaxf(m, sc[t]);
#pragma unroll
    for (int o = 16; o; o >>= 1) m = fmaxf(m, __shfl_xor_sync(0xffffffffu, m, o));
    if (lane == 0) rr[wid] = m;
    __syncthreads();
    if (tid == 0) {
        float mm = rr[0];
#pragma unroll
        for (int w = 1; w < 8; w++) mm = fmaxf(mm, rr[w]);
        fin[0] = mm;
    }
    __syncthreads();
    m = fin[0];

    // exp + sum
    float s = 0.f;
    for (int t = tid; t <= T; t += NTHREADS) {
        float e = __expf(sc[t] - m);
        sc[t] = e;
        s += e;
    }
#pragma unroll
    for (int o = 16; o; o >>= 1) s += __shfl_xor_sync(0xffffffffu, s, o);
    if (lane == 0) rr[wid] = s;
    __syncthreads();
    if (tid == 0) {
        float ss = rr[0];
#pragma unroll
        for (int w = 1; w < 8; w++) ss += rr[w];
        fin[1] = 1.0f / ss;
    }
    __syncthreads();
    const float invS = fin[1];

    // V accumulation: warp per timestep, lane = head dim
    float acc = 0.f;
#pragma unroll 4
    for (int t = wid; t < T; t += 8) acc += sc[t] * Vb[(size_t)t * HD + lane];
    if (wid == 0) acc += sc[T] * vn[lane];
    redv[wid * HD + lane] = acc;
    __syncthreads();
    if (wid == 0) {
        float o = acc;
#pragma unroll
        for (int w = 1; w < 8; w++) o += redv[w * HD + lane];
        g_attn[(size_t)b * DD + h * HD + lane] = o * invS;
    }
    __syncthreads();
}

// ---------------- LN block: one batch ----------------
// parts!=null: v = g_h + bias + sum of 4 partials; else v = g_h + add (bias already in)
__device__ void ln_block(const float* __restrict__ add, const float* __restrict__ parts,
                         const float* __restrict__ bias,
                         const float* __restrict__ gam, const float* __restrict__ bet,
                         float* __restrict__ out2, int b, float* sm) {
    const int tid = threadIdx.x, lane = tid & 31, wid = tid >> 5;
    float v0, v1;
    {
        int j = tid;
        float t = g_h[(size_t)b * DD + j];
        if (parts) {
            t += bias[j];
#pragma unroll
            for (int sI = 0; sI < 4; sI++) t += parts[(size_t)(sI * BB + b) * DD + j];
        } else t += add[(size_t)b * DD + j];
        v0 = t;
        j = tid + 256;
        t = g_h[(size_t)b * DD + j];
        if (parts) {
            t += bias[j];
#pragma unroll
            for (int sI = 0; sI < 4; sI++) t += parts[(size_t)(sI * BB + b) * DD + j];
        } else t += add[(size_t)b * DD + j];
        v1 = t;
    }
    float s1 = v0 + v1, s2 = v0 * v0 + v1 * v1;
#pragma unroll
    for (int o = 16; o; o >>= 1) {
        s1 += __shfl_xor_sync(0xffffffffu, s1, o);
        s2 += __shfl_xor_sync(0xffffffffu, s2, o);
    }
    float* rs = sm;       // [8]
    float* rq = sm + 8;   // [8]
    float* mv = sm + 16;  // [2]
    if (lane == 0) { rs[wid] = s1; rq[wid] = s2; }
    __syncthreads();
    if (tid == 0) {
        float a = 0.f, q = 0.f;
#pragma unroll
        for (int w = 0; w < 8; w++) { a += rs[w]; q += rq[w]; }
        float mean = a / DD;
        mv[0] = mean;
        mv[1] = rsqrtf(q / DD - mean * mean + 1e-5f);
    }
    __syncthreads();
    const float mean = mv[0], rstd = mv[1];
    float o0 = (v0 - mean) * rstd * gam[tid] + bet[tid];
    float o1 = (v1 - mean) * rstd * gam[tid + 256] + bet[tid + 256];
    g_h[(size_t)b * DD + tid] = o0;
    g_h[(size_t)b * DD + tid + 256] = o1;
    if (out2) {
        out2[(size_t)b * DD + tid] = o0;
        out2[(size_t)b * DD + tid + 256] = o1;
    }
    __syncthreads();
}

// ---------------- persistent kernel ----------------
__global__ void __launch_bounds__(NTHREADS, 2)
decoder_kernel(const float* __restrict__ x,
               const float* __restrict__ kc, const float* __restrict__ vc,
               const float* __restrict__ ln1g, const float* __restrict__ ln1b,
               const float* __restrict__ qkvw, const float* __restrict__ qkvb,
               const float* __restrict__ outw, const float* __restrict__ outb,
               const float* __restrict__ ln2g, const float* __restrict__ ln2b,
               const float* __restrict__ w1, const float* __restrict__ b1,
               const float* __restrict__ w2, const float* __restrict__ b2,
               const int* __restrict__ kvlen, float* __restrict__ dout) {
    extern __shared__ float sm[];

    // S0: h <- x
    for (int i = blockIdx.x * NTHREADS + threadIdx.x; i < BB * DD;
         i += gridDim.x * NTHREADS)
        g_h[i] = x[i];
    gsync();

    for (int l = 0; l < LL; l++) {
        const float* Wq = qkvw + (size_t)l * DD * NQKV;
        const float* bq = qkvb + (size_t)l * NQKV;
        const float* Wo = outw + (size_t)l * DD * DD;
        const float* bo = outb + (size_t)l * DD;
        const float* W1 = w1 + (size_t)l * DD * DFF;
        const float* B1 = b1 + (size_t)l * DFF;
        const float* W2 = w2 + (size_t)l * DFF * DD;
        const float* B2 = b2 + (size_t)l * DD;
        const float* Kc = kc + (size_t)l * BB * HH * TMAX * HD;
        const float* Vc = vc + (size_t)l * BB * HH * TMAX * HD;

        // S1 qkv: 48 colgroups x 2 batchgroups = 96 vblocks
        for (int vb = blockIdx.x; vb < 96; vb += gridDim.x) {
            int c0 = (vb >> 1) * 32, b0 = (vb & 1) * 8;
            gemv_block(g_h, DD, 0, Wq, NQKV, bq, 0, g_qkv, NQKV, b0, c0, sm);
        }
        gsync();

        // S2 attention: 256 (b,h) vblocks
        for (int vb = blockIdx.x; vb < 256; vb += gridDim.x)
            attn_block(Kc, Vc, kvlen, vb >> 4, vb & 15, sm);
        gsync();

        // S3 out projection: 16 x 2 = 32 vblocks (bias folded in)
        for (int vb = blockIdx.x; vb < 32; vb += gridDim.x) {
            int c0 = (vb >> 1) * 32, b0 = (vb & 1) * 8;
            gemv_block(g_attn, DD, 0, Wo, DD, bo, 0, g_ao, DD, b0, c0, sm);
        }
        gsync();

        // S4 LN1: 16 vblocks
        for (int vb = blockIdx.x; vb < 16; vb += gridDim.x)
            ln_block(g_ao, nullptr, nullptr, ln1g + (size_t)l * DD,
                     ln1b + (size_t)l * DD, nullptr, vb, sm);
        gsync();

        // S5 mlp1: 64 x 2 = 128 vblocks (bias + relu fused)
        for (int vb = blockIdx.x; vb < 128; vb += gridDim.x) {
            int c0 = (vb >> 1) * 32, b0 = (vb & 1) * 8;
            gemv_block(g_h, DD, 0, W1, DFF, B1, 1, g_act, DFF, b0, c0, sm);
        }
        gsync();

        // S6 mlp2: 16 colgroups x 2 batchgroups x 4 K-slices = 128 vblocks
        for (int vb = blockIdx.x; vb < 128; vb += gridDim.x) {
            int ks = vb & 3, b0 = ((vb >> 2) & 1) * 8, c0 = (vb >> 3) * 32;
            gemv_block(g_act, DFF, ks * 512, W2, DD, nullptr, 0,
                       g_p2 + (size_t)ks * BB * DD, DD, b0, c0, sm);
        }
        gsync();

        // S7 LN2 (merges 4 partials): 16 vblocks; last layer also writes d_out
        for (int vb = blockIdx.x; vb < 16; vb += gridDim.x)
            ln_block(nullptr, g_p2, B2, ln2g + (size_t)l * DD,
                     ln2b + (size_t)l * DD,
                     (l == LL - 1) ? dout : nullptr, vb, sm);
        gsync();
    }
}

// ---------------- launcher ----------------
extern "C" void kernel_launch(void* const* d_in, const int* in_sizes, int n_in,
                              void* d_out, int out_size) {
    (void)in_sizes; (void)n_in; (void)out_size;
    const float* x    = (const float*)d_in[0];
    const float* kc   = (const float*)d_in[1];
    const float* vc   = (const float*)d_in[2];
    const float* ln1g = (const float*)d_in[3];
    const float* ln1b = (const float*)d_in[4];
    const float* qkvw = (const float*)d_in[5];
    const float* qkvb = (const float*)d_in[6];
    const float* outw = (const float*)d_in[7];
    const float* outb = (const float*)d_in[8];
    const float* ln2g = (const float*)d_in[9];
    const float* ln2b = (const float*)d_in[10];
    const float* w1   = (const float*)d_in[11];
    const float* b1   = (const float*)d_in[12];
    const float* w2   = (const float*)d_in[13];
    const float* b2   = (const float*)d_in[14];
    const int* kvlen  = (const int*)d_in[16];

    static int grid = 0;
    const int SMEM = (512 * 12 + 256 * 9) * 4;  // 33792 bytes
    if (!grid) {
        cudaFuncSetAttribute(decoder_kernel,
                             cudaFuncAttributeMaxDynamicSharedMemorySize, SMEM);
        int dev = 0;
        cudaGetDevice(&dev);
        cudaDeviceProp prop;
        cudaGetDeviceProperties(&prop, dev);
        int occ = 0;
        cudaOccupancyMaxActiveBlocksPerMultiprocessor(&occ, decoder_kernel,
                                                      NTHREADS, SMEM);
        if (occ < 1) occ = 1;
        if (occ > 2) occ = 2;
        grid = prop.multiProcessorCount * occ;
    }

    decoder_kernel<<<grid, NTHREADS, SMEM>>>(
        x, kc, vc, ln1g, ln1b, qkvw, qkvb, outw, outb, ln2g, ln2b,
        w1, b1, w2, b2, kvlen, (float*)d_out);
}

// round 3
// speedup vs baseline: 3.1805x; 1.4024x over previous
#include <cuda_runtime.h>
#include <math.h>

#define BB 16
#define DD 512
#define HH 16
#define HD 32
#define LL 24
#define DFF 2048
#define NQKV 1536
#define TMAX 1024
#define NT 256

// ---------------- device scratch ----------------
__device__ float g_res[BB * DD];     // layer input h2 (normalized)
__device__ float g_h1[BB * DD];      // post-LN1 hidden
__device__ float g_qkv[BB * NQKV];
__device__ float g_attn[BB * DD];
__device__ float g_act[BB * DFF];    // relu(mlp1)
__device__ float g_po[4 * BB * DD];  // outproj K-partials
__device__ float g_p2[8 * BB * DD];  // mlp2 K-partials
__device__ unsigned g_bar_count;
__device__ volatile unsigned g_bar_gen;

// ---------------- grid barrier (all blocks resident) ----------------
__device__ __forceinline__ void gsync() {
    __syncthreads();
    if (threadIdx.x == 0) {
        unsigned gen = g_bar_gen;
        __threadfence();
        if (atomicAdd(&g_bar_count, 1u) == gridDim.x - 1) {
            g_bar_count = 0;
            __threadfence();
            g_bar_gen = gen + 1;
        } else {
            while (g_bar_gen == gen) { }
            __threadfence();
        }
    }
    __syncthreads();
}

// ---------------- preload: plain copy src[b][d0+d] -> xs[d][bb] ----------
template <int DS>
__device__ __forceinline__ void preload_plain(const float* __restrict__ src, int ld,
                                              int d0, int b0, float* xs,
                                              float* __restrict__ wout) {
    const int tid = threadIdx.x;
#pragma unroll
    for (int i = tid; i < DS * 8; i += NT) {
        int bb = i / DS, d = i - bb * DS;
        float v = src[(size_t)(b0 + bb) * ld + d0 + d];
        xs[d * 12 + bb] = v;
        if (wout) wout[(size_t)(b0 + bb) * DS + d] = v;
    }
    __syncthreads();
}

// ---------------- preload with fused LN merge (K = 512 only) -------------
// v[d] = base[b][d] + bias[d] + sum_{s<S} part[s][b][d];  LN(v) -> xs
// warp w handles batch b0+w. If wout, also writes normalized row.
template <int S>
__device__ __forceinline__ void preload_ln(const float* __restrict__ base,
                                           const float* __restrict__ bias,
                                           const float* __restrict__ part,
                                           const float* __restrict__ gam,
                                           const float* __restrict__ bet,
                                           int b0, float* xs,
                                           float* __restrict__ wout) {
    const int lane = threadIdx.x & 31, w = threadIdx.x >> 5;
    const int b = b0 + w;
    float vals[16];
    float s1 = 0.f, s2 = 0.f;
#pragma unroll
    for (int j = 0; j < 16; j++) {
        int d = lane + j * 32;
        float v = base[(size_t)b * DD + d] + bias[d];
#pragma unroll
        for (int s = 0; s < S; s++) v += part[(size_t)(s * BB + b) * DD + d];
        vals[j] = v;
        s1 += v;
        s2 += v * v;
    }
#pragma unroll
    for (int o = 16; o; o >>= 1) {
        s1 += __shfl_xor_sync(0xffffffffu, s1, o);
        s2 += __shfl_xor_sync(0xffffffffu, s2, o);
    }
    const float mean = s1 * (1.0f / DD);
    const float rstd = rsqrtf(s2 * (1.0f / DD) - mean * mean + 1e-5f);
#pragma unroll
    for (int j = 0; j < 16; j++) {
        int d = lane + j * 32;
        float o = (vals[j] - mean) * rstd * gam[d] + bet[d];
        xs[d * 12 + w] = o;
        if (wout) wout[(size_t)b * DD + d] = o;
    }
    __syncthreads();
}

// ---------------- gemv core: 32 cols x 8 batches over DS K-dims ----------
template <int DS>
__device__ __forceinline__ void gemv_core(const float* __restrict__ W, int N,
                                          int d0, int c0,
                                          const float* __restrict__ bias, int relu,
                                          float* __restrict__ out, int ldo,
                                          int b0, float* xs, float* red) {
    const int tid = threadIdx.x, lane = tid & 31, w = tid >> 5;
    constexpr int DW = DS / 8;
    const float* Wp = W + (size_t)(d0 + w * DW) * N + c0 + lane;
    const float* xp = xs + (size_t)(w * DW) * 12;
    float a0 = 0, a1 = 0, a2 = 0, a3 = 0, a4 = 0, a5 = 0, a6 = 0, a7 = 0;
#pragma unroll 8
    for (int d = 0; d < DW; d++) {
        float wv = Wp[(size_t)d * N];
        float4 xa = *(const float4*)(xp + d * 12);
        float4 xb = *(const float4*)(xp + d * 12 + 4);
        a0 += xa.x * wv; a1 += xa.y * wv; a2 += xa.z * wv; a3 += xa.w * wv;
        a4 += xb.x * wv; a5 += xb.y * wv; a6 += xb.z * wv; a7 += xb.w * wv;
    }
    float* rp = red + (size_t)tid * 9;
    rp[0] = a0; rp[1] = a1; rp[2] = a2; rp[3] = a3;
    rp[4] = a4; rp[5] = a5; rp[6] = a6; rp[7] = a7;
    __syncthreads();
    const int cc = tid & 31, bb = tid >> 5;
    float v = 0.f;
#pragma unroll
    for (int w2 = 0; w2 < 8; w2++) v += red[(size_t)(w2 * 32 + cc) * 9 + bb];
    if (bias) v += bias[c0 + cc];
    if (relu) v = fmaxf(v, 0.f);
    out[(size_t)(b0 + bb) * ldo + c0 + cc] = v;
    __syncthreads();
}

// ---------------- attention block: one (b, h) ----------------
__device__ void attn_block(const float* __restrict__ Kc, const float* __restrict__ Vc,
                           const int* __restrict__ kvlen, int b, int h, float* sm) {
    float* sc   = sm;          // [1056]
    float* qs   = sm + 1056;   // [32]
    float* redv = sm + 1088;   // [8][32]
    float* rr   = sm + 1344;   // [8]
    float* fin  = sm + 1352;   // [2]

    const int tid = threadIdx.x, wid = tid >> 5, lane = tid & 31;
    const int T = kvlen[b];
    const float scale = 0.17677669529663687f;

    if (tid < HD) qs[tid] = g_qkv[(size_t)b * NQKV + h * HD + tid];
    __syncthreads();

    const float* Kb = Kc + ((size_t)b * HH + h) * TMAX * HD;
    const float* Vb = Vc + ((size_t)b * HH + h) * TMAX * HD;
    const float* kn = g_qkv + (size_t)b * NQKV + DD + h * HD;
    const float* vn = g_qkv + (size_t)b * NQKV + 2 * DD + h * HD;

    // score pass: thread per timestep
    for (int t = tid; t <= T; t += NT) {
        const float* kp = (t < T) ? (Kb + (size_t)t * HD) : kn;
        float s = 0.f;
#pragma unroll
        for (int i = 0; i < 8; i++) {
            float4 k4 = *(const float4*)(kp + i * 4);
            float4 q4 = *(const float4*)(qs + i * 4);
            s += k4.x * q4.x + k4.y * q4.y + k4.z * q4.z + k4.w * q4.w;
        }
        sc[t] = s * scale;
    }
    __syncthreads();

    // block max
    float m = -1e30f;
    for (int t = tid; t <= T; t += NT) m = fmaxf(m, sc[t]);
#pragma unroll
    for (int o = 16; o; o >>= 1) m = fmaxf(m, __shfl_xor_sync(0xffffffffu, m, o));
    if (lane == 0) rr[wid] = m;
    __syncthreads();
    if (tid == 0) {
        float mm = rr[0];
#pragma unroll
        for (int w = 1; w < 8; w++) mm = fmaxf(mm, rr[w]);
        fin[0] = mm;
    }
    __syncthreads();
    m = fin[0];

    // exp + sum
    float s = 0.f;
    for (int t = tid; t <= T; t += NT) {
        float e = __expf(sc[t] - m);
        sc[t] = e;
        s += e;
    }
#pragma unroll
    for (int o = 16; o; o >>= 1) s += __shfl_xor_sync(0xffffffffu, s, o);
    if (lane == 0) rr[wid] = s;
    __syncthreads();
    if (tid == 0) {
        float ss = rr[0];
#pragma unroll
        for (int w = 1; w < 8; w++) ss += rr[w];
        fin[1] = 1.0f / ss;
    }
    __syncthreads();
    const float invS = fin[1];

    // V pass: warp covers 4 timesteps/iter; lane = (t-subgroup, dim-quad)
    const int tq = lane >> 3;      // 0..3
    const int dq = lane & 7;       // 0..7
    float4 acc = make_float4(0.f, 0.f, 0.f, 0.f);
#pragma unroll 4
    for (int t = wid * 4 + tq; t < T; t += 32) {
        float wgt = sc[t];
        float4 v4 = *(const float4*)(Vb + (size_t)t * HD + dq * 4);
        acc.x += wgt * v4.x; acc.y += wgt * v4.y;
        acc.z += wgt * v4.z; acc.w += wgt * v4.w;
    }
    if (wid == 0 && tq == 0) {  // new token at t == T
        float wgt = sc[T];
        float4 v4 = *(const float4*)(vn + dq * 4);
        acc.x += wgt * v4.x; acc.y += wgt * v4.y;
        acc.z += wgt * v4.z; acc.w += wgt * v4.w;
    }
#pragma unroll
    for (int o = 8; o <= 16; o <<= 1) {
        acc.x += __shfl_xor_sync(0xffffffffu, acc.x, o);
        acc.y += __shfl_xor_sync(0xffffffffu, acc.y, o);
        acc.z += __shfl_xor_sync(0xffffffffu, acc.z, o);
        acc.w += __shfl_xor_sync(0xffffffffu, acc.w, o);
    }
    if (tq == 0) *(float4*)(redv + wid * 32 + dq * 4) = acc;
    __syncthreads();
    if (tid < HD) {
        float o = 0.f;
#pragma unroll
        for (int w = 0; w < 8; w++) o += redv[w * 32 + tid];
        g_attn[(size_t)b * DD + h * HD + tid] = o * invS;
    }
    __syncthreads();
}

// ---------------- final LN (writes d_out) ----------------
__device__ void final_ln(const float* __restrict__ bias,
                         const float* __restrict__ gam,
                         const float* __restrict__ bet,
                         float* __restrict__ dout, int b, float* sm) {
    const int tid = threadIdx.x, lane = tid & 31, wid = tid >> 5;
    float v0, v1;
    {
        int j = tid;
        float t = g_h1[(size_t)b * DD + j] + bias[j];
#pragma unroll
        for (int s = 0; s < 8; s++) t += g_p2[(size_t)(s * BB + b) * DD + j];
        v0 = t;
        j = tid + 256;
        t = g_h1[(size_t)b * DD + j] + bias[j];
#pragma unroll
        for (int s = 0; s < 8; s++) t += g_p2[(size_t)(s * BB + b) * DD + j];
        v1 = t;
    }
    float s1 = v0 + v1, s2 = v0 * v0 + v1 * v1;
#pragma unroll
    for (int o = 16; o; o >>= 1) {
        s1 += __shfl_xor_sync(0xffffffffu, s1, o);
        s2 += __shfl_xor_sync(0xffffffffu, s2, o);
    }
    float* rs = sm; float* rq = sm + 8; float* mv = sm + 16;
    if (lane == 0) { rs[wid] = s1; rq[wid] = s2; }
    __syncthreads();
    if (tid == 0) {
        float a = 0.f, q = 0.f;
#pragma unroll
        for (int w = 0; w < 8; w++) { a += rs[w]; q += rq[w]; }
        float mean = a / DD;
        mv[0] = mean;
        mv[1] = rsqrtf(q / DD - mean * mean + 1e-5f);
    }
    __syncthreads();
    const float mean = mv[0], rstd = mv[1];
    dout[(size_t)b * DD + tid] = (v0 - mean) * rstd * gam[tid] + bet[tid];
    dout[(size_t)b * DD + tid + 256] = (v1 - mean) * rstd * gam[tid + 256] + bet[tid + 256];
    __syncthreads();
}

// ---------------- persistent kernel ----------------
__global__ void __launch_bounds__(NT, 2)
decoder_kernel(const float* __restrict__ x,
               const float* __restrict__ kc, const float* __restrict__ vc,
               const float* __restrict__ ln1g, const float* __restrict__ ln1b,
               const float* __restrict__ qkvw, const float* __restrict__ qkvb,
               const float* __restrict__ outw, const float* __restrict__ outb,
               const float* __restrict__ ln2g, const float* __restrict__ ln2b,
               const float* __restrict__ w1, const float* __restrict__ b1,
               const float* __restrict__ w2, const float* __restrict__ b2,
               const int* __restrict__ kvlen, float* __restrict__ dout) {
    extern __shared__ float sm[];
    float* xs  = sm;             // [512][12]
    float* red = sm + 512 * 12;  // [256][9]

    for (int l = 0; l < LL; l++) {
        const float* Wq = qkvw + (size_t)l * DD * NQKV;
        const float* bq = qkvb + (size_t)l * NQKV;
        const float* Wo = outw + (size_t)l * DD * DD;
        const float* bo = outb + (size_t)l * DD;
        const float* W1 = w1 + (size_t)l * DD * DFF;
        const float* B1 = b1 + (size_t)l * DFF;
        const float* W2 = w2 + (size_t)l * DFF * DD;
        const float* Kc = kc + (size_t)l * BB * HH * TMAX * HD;
        const float* Vc = vc + (size_t)l * BB * HH * TMAX * HD;

        // S1: qkv GEMV, LN2(prev layer) fused into preload. 96 vblocks.
        for (int vb = blockIdx.x; vb < 96; vb += gridDim.x) {
            int c0 = (vb >> 1) * 32, b0 = (vb & 1) * 8;
            float* wo = (c0 == 0) ? g_res : nullptr;
            if (l == 0)
                preload_plain<512>(x, DD, 0, b0, xs, wo);
            else
                preload_ln<8>(g_h1, b2 + (size_t)(l - 1) * DD, g_p2,
                              ln2g + (size_t)(l - 1) * DD, ln2b + (size_t)(l - 1) * DD,
                              b0, xs, wo);
            gemv_core<512>(Wq, NQKV, 0, c0, bq, 0, g_qkv, NQKV, b0, xs, red);
        }
        gsync();

        // S2: attention. 256 vblocks.
        for (int vb = blockIdx.x; vb < 256; vb += gridDim.x)
            attn_block(Kc, Vc, kvlen, vb >> 4, vb & 15, sm);
        gsync();

        // S3: outproj partials, K split 4. 128 vblocks.
        for (int vb = blockIdx.x; vb < 128; vb += gridDim.x) {
            int ks = vb & 3, b0 = ((vb >> 2) & 1) * 8, c0 = (vb >> 3) * 32;
            preload_plain<128>(g_attn, DD, ks * 128, b0, xs, nullptr);
            gemv_core<128>(Wo, DD, ks * 128, c0, nullptr, 0,
                           g_po + (size_t)ks * BB * DD, DD, b0, xs, red);
        }
        gsync();

        // S4: mlp1 GEMV, LN1 fused into preload (merges 4 outproj partials,
        // residual g_res, bias bo). 128 vblocks. relu+b1 in epilogue.
        for (int vb = blockIdx.x; vb < 128; vb += gridDim.x) {
            int c0 = (vb >> 1) * 32, b0 = (vb & 1) * 8;
            float* wo = (c0 == 0) ? g_h1 : nullptr;
            preload_ln<4>(g_res, bo, g_po,
                          ln1g + (size_t)l * DD, ln1b + (size_t)l * DD,
                          b0, xs, wo);
            gemv_core<512>(W1, DFF, 0, c0, B1, 1, g_act, DFF, b0, xs, red);
        }
        gsync();

        // S5: mlp2 partials, K split 8. 256 vblocks.
        for (int vb = blockIdx.x; vb < 256; vb += gridDim.x) {
            int ks = vb & 7, b0 = ((vb >> 3) & 1) * 8, c0 = (vb >> 4) * 32;
            preload_plain<256>(g_act, DFF, ks * 256, b0, xs, nullptr);
            gemv_core<256>(W2, DD, ks * 256, c0, nullptr, 0,
                           g_p2 + (size_t)ks * BB * DD, DD, b0, xs, red);
        }
        gsync();
    }

    // final LN2 of last layer -> d_out. 16 vblocks.
    for (int vb = blockIdx.x; vb < 16; vb += gridDim.x)
        final_ln(b2 + (size_t)(LL - 1) * DD,
                 ln2g + (size_t)(LL - 1) * DD, ln2b + (size_t)(LL - 1) * DD,
                 dout, vb, sm);
}

// ---------------- launcher ----------------
extern "C" void kernel_launch(void* const* d_in, const int* in_sizes, int n_in,
                              void* d_out, int out_size) {
    (void)in_sizes; (void)n_in; (void)out_size;
    const float* x    = (const float*)d_in[0];
    const float* kc   = (const float*)d_in[1];
    const float* vc   = (const float*)d_in[2];
    const float* ln1g = (const float*)d_in[3];
    const float* ln1b = (const float*)d_in[4];
    const float* qkvw = (const float*)d_in[5];
    const float* qkvb = (const float*)d_in[6];
    const float* outw = (const float*)d_in[7];
    const float* outb = (const float*)d_in[8];
    const float* ln2g = (const float*)d_in[9];
    const float* ln2b = (const float*)d_in[10];
    const float* w1   = (const float*)d_in[11];
    const float* b1   = (const float*)d_in[12];
    const float* w2   = (const float*)d_in[13];
    const float* b2   = (const float*)d_in[14];
    const int* kvlen  = (const int*)d_in[16];

    static int grid = 0;
    const int SMEM = (512 * 12 + 256 * 9) * 4;  // 33792 bytes
    if (!grid) {
        cudaFuncSetAttribute(decoder_kernel,
                             cudaFuncAttributeMaxDynamicSharedMemorySize, SMEM);
        int dev = 0;
        cudaGetDevice(&dev);
        cudaDeviceProp prop;
        cudaGetDeviceProperties(&prop, dev);
        int occ = 0;
        cudaOccupancyMaxActiveBlocksPerMultiprocessor(&occ, decoder_kernel,
                                                      NT, SMEM);
        if (occ < 1) occ = 1;
        if (occ > 2) occ = 2;
        grid = prop.multiProcessorCount * occ;
    }

    decoder_kernel<<<grid, NT, SMEM>>>(
        x, kc, vc, ln1g, ln1b, qkvw, qkvb, outw, outb, ln2g, ln2b,
        w1, b1, w2, b2, kvlen, (float*)d_out);
}

// round 4
// speedup vs baseline: 3.3456x; 1.0519x over previous
#include <cuda_runtime.h>
#include <math.h>

#define BB 16
#define DD 512
#define HH 16
#define HD 32
#define LL 24
#define DFF 2048
#define NQKV 1536
#define TMAX 1024
#define NT 256
#define NCH 4  // attention T-chunks

// ---------------- device scratch ----------------
__device__ float g_h[BB * DD];            // layer input (post LN2 of prev layer)
__device__ float g_h1[BB * DD];           // post-LN1 hidden
__device__ float g_pqkv[8 * BB * NQKV];   // qkv K-partials
__device__ float g_po[16 * BB * DD];      // outproj K-partials
__device__ float g_pm1[4 * BB * DFF];     // mlp1 K-partials
__device__ float g_p2[16 * BB * DD];      // mlp2 K-partials
__device__ float g_am[BB * HH * NCH];     // per-chunk softmax max
__device__ float g_as[BB * HH * NCH];     // per-chunk exp-sum
__device__ float g_ao[NCH * BB * HH * HD];// per-chunk unnormalized V-acc
__device__ unsigned g_bar_count;
__device__ volatile unsigned g_bar_gen;

// ---------------- grid barrier ----------------
__device__ __forceinline__ void gsync() {
    __syncthreads();
    if (threadIdx.x == 0) {
        unsigned gen = g_bar_gen;
        __threadfence();
        if (atomicAdd(&g_bar_count, 1u) == gridDim.x - 1) {
            g_bar_count = 0;
            __threadfence();
            g_bar_gen = gen + 1;
        } else {
            while (g_bar_gen == gen) __nanosleep(64);
            __threadfence();
        }
    }
    __syncthreads();
}

// ---------------- plain preload: src[b][d0+d] -> xs[d][bb] ----------------
template <int DS>
__device__ __forceinline__ void preload_plain(const float* __restrict__ src, int ld,
                                              int d0, int b0, float* xs) {
    const int tid = threadIdx.x;
#pragma unroll
    for (int i = tid; i < DS * 8; i += NT) {
        int bb = i / DS, d = i % DS;
        xs[d * 12 + bb] = src[(size_t)(b0 + bb) * ld + d0 + d];
    }
    __syncthreads();
}

// ---------------- mlp2 preload: relu(b1 + sum of 4 mlp1 partials) --------
__device__ __forceinline__ void preload_relu(const float* __restrict__ b1,
                                             int d0, int b0, float* xs) {
    const int tid = threadIdx.x;
#pragma unroll
    for (int i = tid; i < 128 * 8; i += NT) {
        int bb = i >> 7, d = i & 127;
        int gd = d0 + d;
        float v = b1[gd];
#pragma unroll
        for (int s = 0; s < 4; s++)
            v += g_pm1[(size_t)(s * BB + b0 + bb) * DFF + gd];
        xs[d * 12 + bb] = fmaxf(v, 0.f);
    }
    __syncthreads();
}

// ---------------- outproj preload: merge NCH attention chunks ------------
// DS=32, d0 = h*32 exactly; element (bb, j).
__device__ __forceinline__ void preload_attn(int h, int b0, float* xs) {
    const int tid = threadIdx.x;
    const int bb = tid >> 5, j = tid & 31;
    const int b = b0 + bb;
    const int base = (b * HH + h) * NCH;
    float m0 = g_am[base + 0], m1 = g_am[base + 1];
    float m2 = g_am[base + 2], m3 = g_am[base + 3];
    float m = fmaxf(fmaxf(m0, m1), fmaxf(m2, m3));
    float w0 = __expf(m0 - m), w1 = __expf(m1 - m);
    float w2 = __expf(m2 - m), w3 = __expf(m3 - m);
    float S = g_as[base + 0] * w0 + g_as[base + 1] * w1 +
              g_as[base + 2] * w2 + g_as[base + 3] * w3;
    const size_t ob = ((size_t)b * HH + h) * HD + j;
    float o = g_ao[(size_t)(0 * BB) * HH * HD + ob] * w0 +
              g_ao[(size_t)(1 * BB) * HH * HD + ob] * w1 +
              g_ao[(size_t)(2 * BB) * HH * HD + ob] * w2 +
              g_ao[(size_t)(3 * BB) * HH * HD + ob] * w3;
    xs[j * 12 + bb] = o / S;
    __syncthreads();
}

// ---------------- gemv core: 32 cols x 8 batches over DS K-dims ----------
template <int DS>
__device__ __forceinline__ void gemv_core(const float* __restrict__ W, int N,
                                          int d0, int c0,
                                          float* __restrict__ out, int ldo,
                                          int b0, float* xs, float* red) {
    const int tid = threadIdx.x, lane = tid & 31, w = tid >> 5;
    constexpr int DW = DS / 8;
    const float* Wp = W + (size_t)(d0 + w * DW) * N + c0 + lane;
    const float* xp = xs + (size_t)(w * DW) * 12;
    float a0 = 0, a1 = 0, a2 = 0, a3 = 0, a4 = 0, a5 = 0, a6 = 0, a7 = 0;
#pragma unroll
    for (int d = 0; d < DW; d++) {
        float wv = Wp[(size_t)d * N];
        float4 xa = *(const float4*)(xp + d * 12);
        float4 xb = *(const float4*)(xp + d * 12 + 4);
        a0 += xa.x * wv; a1 += xa.y * wv; a2 += xa.z * wv; a3 += xa.w * wv;
        a4 += xb.x * wv; a5 += xb.y * wv; a6 += xb.z * wv; a7 += xb.w * wv;
    }
    float* rp = red + (size_t)tid * 9;
    rp[0] = a0; rp[1] = a1; rp[2] = a2; rp[3] = a3;
    rp[4] = a4; rp[5] = a5; rp[6] = a6; rp[7] = a7;
    __syncthreads();
    const int cc = tid & 31, bb = tid >> 5;
    float v = 0.f;
#pragma unroll
    for (int w2 = 0; w2 < 8; w2++) v += red[(size_t)(w2 * 32 + cc) * 9 + bb];
    out[(size_t)(b0 + bb) * ldo + c0 + cc] = v;
    __syncthreads();
}

// ---------------- attention chunk: one (b, h, c) ----------------
__device__ void attn_chunk(const float* __restrict__ Kc, const float* __restrict__ Vc,
                           const float* __restrict__ bq,
                           const int* __restrict__ kvlen,
                           int b, int h, int c, float* sm) {
    float* sc   = sm;         // [260]
    float* qs   = sm + 264;   // [32]
    float* kns  = sm + 296;   // [32]
    float* vns  = sm + 328;   // [32]
    float* redv = sm + 360;   // [8][32]
    float* rr   = sm + 616;   // [8]
    float* fin  = sm + 624;   // [2]

    const int tid = threadIdx.x, wid = tid >> 5, lane = tid & 31;
    const int T = kvlen[b];
    const int Ttot = T + 1;
    const int CH = (Ttot + NCH - 1) / NCH;
    const int t0 = c * CH;
    const int t1 = (t0 + CH < Ttot) ? (t0 + CH) : Ttot;
    const float scale = 0.17677669529663687f;

    // merge qkv partials for q / k_new / v_new
    if (tid < 96) {
        int which = tid >> 5, j = tid & 31;
        int col = which * DD + h * HD + j;
        float v = bq[col];
#pragma unroll
        for (int s = 0; s < 8; s++) v += g_pqkv[(size_t)(s * BB + b) * NQKV + col];
        if (which == 0) qs[j] = v;
        else if (which == 1) kns[j] = v;
        else vns[j] = v;
    }
    __syncthreads();

    const int outi = (b * HH + h) * NCH + c;
    const size_t ob = ((size_t)b * HH + h) * HD;

    if (t1 <= t0) {  // empty chunk (uniform branch)
        if (tid == 0) { g_am[outi] = -1e30f; g_as[outi] = 0.f; }
        if (tid < HD) g_ao[(size_t)(c * BB) * HH * HD + ob + tid] = 0.f;
        return;
    }

    const float* Kb = Kc + ((size_t)b * HH + h) * TMAX * HD;
    const float* Vb = Vc + ((size_t)b * HH + h) * TMAX * HD;
    const int len = t1 - t0;

    // score pass: thread per timestep
    for (int t = t0 + tid; t < t1; t += NT) {
        const float* kp = (t < T) ? (Kb + (size_t)t * HD) : kns;
        float s = 0.f;
#pragma unroll
        for (int i = 0; i < 8; i++) {
            float4 k4 = *(const float4*)(kp + i * 4);
            float4 q4 = *(const float4*)(qs + i * 4);
            s += k4.x * q4.x + k4.y * q4.y + k4.z * q4.z + k4.w * q4.w;
        }
        sc[t - t0] = s * scale;
    }
    __syncthreads();

    // chunk max
    float m = -1e30f;
    for (int i = tid; i < len; i += NT) m = fmaxf(m, sc[i]);
#pragma unroll
    for (int o = 16; o; o >>= 1) m = fmaxf(m, __shfl_xor_sync(0xffffffffu, m, o));
    if (lane == 0) rr[wid] = m;
    __syncthreads();
    if (tid == 0) {
        float mm = rr[0];
#pragma unroll
        for (int w = 1; w < 8; w++) mm = fmaxf(mm, rr[w]);
        fin[0] = mm;
    }
    __syncthreads();
    m = fin[0];

    // exp + sum
    float s = 0.f;
    for (int i = tid; i < len; i += NT) {
        float e = __expf(sc[i] - m);
        sc[i] = e;
        s += e;
    }
#pragma unroll
    for (int o = 16; o; o >>= 1) s += __shfl_xor_sync(0xffffffffu, s, o);
    if (lane == 0) rr[wid] = s;
    __syncthreads();
    if (tid == 0) {
        float ss = rr[0];
#pragma unroll
        for (int w = 1; w < 8; w++) ss += rr[w];
        g_am[outi] = m;
        g_as[outi] = ss;
    }

    // V pass: warp covers 4 timesteps/iter (unnormalized accumulation)
    const int tq = lane >> 3, dq = lane & 7;
    float4 acc = make_float4(0.f, 0.f, 0.f, 0.f);
    for (int t = t0 + wid * 4 + tq; t < t1; t += 32) {
        float wgt = sc[t - t0];
        const float* vp = (t < T) ? (Vb + (size_t)t * HD) : vns;
        float4 v4 = *(const float4*)(vp + dq * 4);
        acc.x += wgt * v4.x; acc.y += wgt * v4.y;
        acc.z += wgt * v4.z; acc.w += wgt * v4.w;
    }
#pragma unroll
    for (int o = 8; o <= 16; o <<= 1) {
        acc.x += __shfl_xor_sync(0xffffffffu, acc.x, o);
        acc.y += __shfl_xor_sync(0xffffffffu, acc.y, o);
        acc.z += __shfl_xor_sync(0xffffffffu, acc.z, o);
        acc.w += __shfl_xor_sync(0xffffffffu, acc.w, o);
    }
    if (tq == 0) *(float4*)(redv + wid * 32 + dq * 4) = acc;
    __syncthreads();
    if (tid < HD) {
        float o = 0.f;
#pragma unroll
        for (int w = 0; w < 8; w++) o += redv[w * 32 + tid];
        g_ao[(size_t)(c * BB) * HH * HD + ob + tid] = o;
    }
}

// ---------------- LN stage: one batch, merge S partials + resid + bias ---
template <int S>
__device__ void ln_stage(const float* __restrict__ part,
                         const float* __restrict__ resid,
                         const float* __restrict__ bias,
                         const float* __restrict__ gam,
                         const float* __restrict__ bet,
                         float* __restrict__ out, int b, float* sm) {
    const int tid = threadIdx.x, lane = tid & 31, wid = tid >> 5;
    float v0, v1;
    {
        int j = tid;
        float t = resid[(size_t)b * DD + j] + bias[j];
#pragma unroll
        for (int s = 0; s < S; s++) t += part[(size_t)(s * BB + b) * DD + j];
        v0 = t;
        j = tid + 256;
        t = resid[(size_t)b * DD + j] + bias[j];
#pragma unroll
        for (int s = 0; s < S; s++) t += part[(size_t)(s * BB + b) * DD + j];
        v1 = t;
    }
    float s1 = v0 + v1, s2 = v0 * v0 + v1 * v1;
#pragma unroll
    for (int o = 16; o; o >>= 1) {
        s1 += __shfl_xor_sync(0xffffffffu, s1, o);
        s2 += __shfl_xor_sync(0xffffffffu, s2, o);
    }
    float* rs = sm; float* rq = sm + 8; float* mv = sm + 16;
    if (lane == 0) { rs[wid] = s1; rq[wid] = s2; }
    __syncthreads();
    if (tid == 0) {
        float a = 0.f, q = 0.f;
#pragma unroll
        for (int w = 0; w < 8; w++) { a += rs[w]; q += rq[w]; }
        float mean = a / DD;
        mv[0] = mean;
        mv[1] = rsqrtf(q / DD - mean * mean + 1e-5f);
    }
    __syncthreads();
    const float mean = mv[0], rstd = mv[1];
    out[(size_t)b * DD + tid] = (v0 - mean) * rstd * gam[tid] + bet[tid];
    out[(size_t)b * DD + tid + 256] =
        (v1 - mean) * rstd * gam[tid + 256] + bet[tid + 256];
    __syncthreads();
}

// ---------------- persistent kernel ----------------
__global__ void __launch_bounds__(NT, 4)
decoder_kernel(const float* __restrict__ x,
               const float* __restrict__ kc, const float* __restrict__ vc,
               const float* __restrict__ ln1g, const float* __restrict__ ln1b,
               const float* __restrict__ qkvw, const float* __restrict__ qkvb,
               const float* __restrict__ outw, const float* __restrict__ outb,
               const float* __restrict__ ln2g, const float* __restrict__ ln2b,
               const float* __restrict__ w1, const float* __restrict__ b1,
               const float* __restrict__ w2, const float* __restrict__ b2,
               const int* __restrict__ kvlen, float* __restrict__ dout) {
    extern __shared__ float sm[];
    float* xs  = sm;             // [128][12] max
    float* red = sm + 128 * 12;  // [256][9]

    for (int l = 0; l < LL; l++) {
        const float* Wq = qkvw + (size_t)l * DD * NQKV;
        const float* bq = qkvb + (size_t)l * NQKV;
        const float* Wo = outw + (size_t)l * DD * DD;
        const float* bo = outb + (size_t)l * DD;
        const float* W1 = w1 + (size_t)l * DD * DFF;
        const float* B1 = b1 + (size_t)l * DFF;
        const float* W2 = w2 + (size_t)l * DFF * DD;
        const float* Kc = kc + (size_t)l * BB * HH * TMAX * HD;
        const float* Vc = vc + (size_t)l * BB * HH * TMAX * HD;

        // S0: produce g_h (x for l==0, else LN2 of prev layer). 16 vblocks.
        if (l == 0) {
            for (int i = blockIdx.x * NT + threadIdx.x; i < BB * DD;
                 i += gridDim.x * NT)
                g_h[i] = x[i];
        } else {
            for (int vb = blockIdx.x; vb < 16; vb += gridDim.x)
                ln_stage<16>(g_p2, g_h1, b2 + (size_t)(l - 1) * DD,
                             ln2g + (size_t)(l - 1) * DD,
                             ln2b + (size_t)(l - 1) * DD, g_h, vb, sm);
        }
        gsync();

        // S1: qkv split-K8 (DS=64). 768 vblocks.
        for (int vb = blockIdx.x; vb < 768; vb += gridDim.x) {
            int ks = vb & 7, b0 = ((vb >> 3) & 1) * 8, c0 = (vb >> 4) * 32;
            preload_plain<64>(g_h, DD, ks * 64, b0, xs);
            gemv_core<64>(Wq, NQKV, ks * 64, c0,
                          g_pqkv + (size_t)ks * BB * NQKV, NQKV, b0, xs, red);
        }
        gsync();

        // S2: attention T-split 4. 1024 vblocks.
        for (int vb = blockIdx.x; vb < 1024; vb += gridDim.x) {
            int c = vb & 3, h = (vb >> 2) & 15, b = vb >> 6;
            attn_chunk(Kc, Vc, bq, kvlen, b, h, c, sm);
        }
        gsync();

        // S3: outproj split-K16 (DS=32), attn merge in preload. 512 vblocks.
        for (int vb = blockIdx.x; vb < 512; vb += gridDim.x) {
            int ks = vb & 15, b0 = ((vb >> 4) & 1) * 8, c0 = (vb >> 5) * 32;
            preload_attn(ks, b0, xs);  // h == ks since DS == HD
            gemv_core<32>(Wo, DD, ks * 32, c0,
                          g_po + (size_t)ks * BB * DD, DD, b0, xs, red);
        }
        gsync();

        // S4: LN1 (merge 16 outproj partials + residual g_h + bo). 16 vblocks.
        for (int vb = blockIdx.x; vb < 16; vb += gridDim.x)
            ln_stage<16>(g_po, g_h, bo, ln1g + (size_t)l * DD,
                         ln1b + (size_t)l * DD, g_h1, vb, sm);
        gsync();

        // S5: mlp1 split-K4 (DS=128). 512 vblocks.
        for (int vb = blockIdx.x; vb < 512; vb += gridDim.x) {
            int ks = vb & 3, b0 = ((vb >> 2) & 1) * 8, c0 = (vb >> 3) * 32;
            preload_plain<128>(g_h1, DD, ks * 128, b0, xs);
            gemv_core<128>(W1, DFF, ks * 128, c0,
                           g_pm1 + (size_t)ks * BB * DFF, DFF, b0, xs, red);
        }
        gsync();

        // S6: mlp2 split-K16 (DS=128), relu+merge in preload. 512 vblocks.
        for (int vb = blockIdx.x; vb < 512; vb += gridDim.x) {
            int ks = vb & 15, b0 = ((vb >> 4) & 1) * 8, c0 = (vb >> 5) * 32;
            preload_relu(B1, ks * 128, b0, xs);
            gemv_core<128>(W2, DD, ks * 128, c0,
                           g_p2 + (size_t)ks * BB * DD, DD, b0, xs, red);
        }
        gsync();
    }

    // final: LN2 of last layer -> d_out. 16 vblocks.
    for (int vb = blockIdx.x; vb < 16; vb += gridDim.x)
        ln_stage<16>(g_p2, g_h1, b2 + (size_t)(LL - 1) * DD,
                     ln2g + (size_t)(LL - 1) * DD,
                     ln2b + (size_t)(LL - 1) * DD, dout, vb, sm);
}

// ---------------- launcher ----------------
extern "C" void kernel_launch(void* const* d_in, const int* in_sizes, int n_in,
                              void* d_out, int out_size) {
    (void)in_sizes; (void)n_in; (void)out_size;
    const float* x    = (const float*)d_in[0];
    const float* kc   = (const float*)d_in[1];
    const float* vc   = (const float*)d_in[2];
    const float* ln1g = (const float*)d_in[3];
    const float* ln1b = (const float*)d_in[4];
    const float* qkvw = (const float*)d_in[5];
    const float* qkvb = (const float*)d_in[6];
    const float* outw = (const float*)d_in[7];
    const float* outb = (const float*)d_in[8];
    const float* ln2g = (const float*)d_in[9];
    const float* ln2b = (const float*)d_in[10];
    const float* w1   = (const float*)d_in[11];
    const float* b1   = (const float*)d_in[12];
    const float* w2   = (const float*)d_in[13];
    const float* b2   = (const float*)d_in[14];
    const int* kvlen  = (const int*)d_in[16];

    static int grid = 0;
    const int SMEM = (128 * 12 + 256 * 9) * 4;  // 15360 bytes
    if (!grid) {
        cudaFuncSetAttribute(decoder_kernel,
                             cudaFuncAttributeMaxDynamicSharedMemorySize, SMEM);
        int dev = 0;
        cudaGetDevice(&dev);
        cudaDeviceProp prop;
        cudaGetDeviceProperties(&prop, dev);
        int occ = 0;
        cudaOccupancyMaxActiveBlocksPerMultiprocessor(&occ, decoder_kernel,
                                                      NT, SMEM);
        if (occ < 1) occ = 1;
        if (occ > 4) occ = 4;
        grid = prop.multiProcessorCount * occ;
    }

    decoder_kernel<<<grid, NT, SMEM>>>(
        x, kc, vc, ln1g, ln1b, qkvw, qkvb, outw, outb, ln2g, ln2b,
        w1, b1, w2, b2, kvlen, (float*)d_out);
}